// round 10
// baseline (speedup 1.0000x reference)
#include <cuda_runtime.h>

#define NN   100000
#define NE   1600000
#define NA   1000
#define NB   ((NN + 255) / 256)
#define FULLMASK 0xffffffffu

// ---------------- scratch (static __device__ globals; no allocs) ----------------
__device__ __align__(16) float g_h1 [NN * 32];   // layer-1 output (all nodes)
__device__ __align__(16) float g_h2 [NN * 32];   // layer-2 output (flagged nodes only)
__device__ float         g_inv[NN];              // 1 / max(indeg, 1)
__device__ int           g_cnt[NN];              // in-degree
__device__ int           g_off[NN];              // CSR row offsets
__device__ int           g_pos[NN];              // placement cursors
__device__ int           g_csr[NE];              // src ids grouped by dst
__device__ unsigned char g_need[NN];             // nodes whose h2 feeds the output cone
__device__ int           g_nlist[NN];            // compacted list of flagged nodes
__device__ int           g_nn;                   // #flagged
__device__ int           g_is64;                 // runtime-detected edge dtype

// ---------------- init + dtype detection (merged; warp-parallel probe) ----------
__global__ void k_init(const void* ei) {
    int v = blockIdx.x * 256 + threadIdx.x;
    if (v < NN) { g_cnt[v] = 0; g_need[v] = (v < NA) ? 1 : 0; }
    if (blockIdx.x == 0 && threadIdx.x < 32) {
        const long long* p = (const long long*)ei;
        unsigned long long w = (unsigned long long)p[threadIdx.x];
        unsigned ok = __ballot_sync(FULLMASK, w < (unsigned long long)NN);
        if (threadIdx.x == 0) { g_is64 = (ok == FULLMASK) ? 1 : 0; g_nn = 0; }
    }
}

// ---------------- count degrees + mark layer-3 cone ----------------
__global__ void k_count(const void* ei) {
    int e = blockIdx.x * 256 + threadIdx.x;
    if (e >= NE) return;
    int src, dst;
    if (g_is64) {
        const long long* p = (const long long*)ei;
        src = (int)p[e]; dst = (int)p[NE + e];
    } else {
        const int* p = (const int*)ei;
        src = p[e]; dst = p[NE + e];
    }
    atomicAdd(&g_cnt[dst], 1);
    if (dst < NA) g_need[src] = 1;
}

// ---------------- single-kernel exclusive scan + finalize ----------------
// 1 block x 1024 threads; thread t owns nodes [t*CH, t*CH+CH). Pass 1: chunk
// sums. Block-scan the 1024 sums (shfl + smem). Pass 2: walk chunk writing
// exclusive offsets, cursors, inv-degree, and the compacted flagged list.
#define SCANT 1024
#define CH    ((NN + SCANT - 1) / SCANT)   // 98
__global__ void __launch_bounds__(SCANT) k_scan() {
    __shared__ int wsum[32];
    int t = threadIdx.x, lane = t & 31, w = t >> 5;
    int beg = t * CH;
    int end = min(beg + CH, NN);

    int sum = 0;
    for (int v = beg; v < end; v++) sum += g_cnt[v];

    // block exclusive scan of per-thread sums
    int s = sum;
#pragma unroll
    for (int d = 1; d < 32; d <<= 1) {
        int q = __shfl_up_sync(FULLMASK, s, d);
        if (lane >= d) s += q;
    }
    if (lane == 31) wsum[w] = s;
    __syncthreads();
    if (w == 0) {
        int a = wsum[lane], u = a;
#pragma unroll
        for (int d = 1; d < 32; d <<= 1) {
            int q = __shfl_up_sync(FULLMASK, u, d);
            if (lane >= d) u += q;
        }
        wsum[lane] = u - a;
    }
    __syncthreads();
    int off = (s - sum) + wsum[w];        // exclusive prefix for this chunk

    for (int v = beg; v < end; v++) {
        int c = g_cnt[v];
        g_off[v] = off;
        g_pos[v] = off;
        g_inv[v] = 1.0f / (float)(c > 1 ? c : 1);
        if (g_need[v]) { int i = atomicAdd(&g_nn, 1); g_nlist[i] = v; }
        off += c;
    }
}

// ---------------- CSR placement ----------------
__global__ void k_place(const void* ei) {
    int e = blockIdx.x * 256 + threadIdx.x;
    if (e >= NE) return;
    int src, dst;
    if (g_is64) {
        const long long* p = (const long long*)ei;
        src = (int)p[e]; dst = (int)p[NE + e];
    } else {
        const int* p = (const int*)ei;
        src = p[e]; dst = p[NE + e];
    }
    int p_ = atomicAdd(&g_pos[dst], 1);
    g_csr[p_] = src;
}

// ---------------- fused gather + node GEMM ----------------
// Round-8 shfl-broadcast structure (proven), but with 4 independent
// accumulator chains so row loads from different chains stay in flight.
__device__ __forceinline__ float gather_mean(const float* __restrict__ X,
                                             int v, int lane) {
    int beg = g_off[v], cnt = g_cnt[v];
    float a0 = 0.f, a1 = 0.f, a2 = 0.f, a3 = 0.f;
    for (int base = 0; base < cnt; base += 32) {
        int idx = base + lane;
        int eid = (idx < cnt) ? g_csr[beg + idx] : 0;
        int n   = min(32, cnt - base);
        int j = 0;
        for (; j + 4 <= n; j += 4) {
            int s0 = __shfl_sync(FULLMASK, eid, j + 0);
            int s1 = __shfl_sync(FULLMASK, eid, j + 1);
            int s2 = __shfl_sync(FULLMASK, eid, j + 2);
            int s3 = __shfl_sync(FULLMASK, eid, j + 3);
            a0 += X[(size_t)s0 * 32 + lane];
            a1 += X[(size_t)s1 * 32 + lane];
            a2 += X[(size_t)s2 * 32 + lane];
            a3 += X[(size_t)s3 * 32 + lane];
        }
        for (; j < n; j++) {
            int s0 = __shfl_sync(FULLMASK, eid, j);
            a0 += X[(size_t)s0 * 32 + lane];
        }
    }
    return ((a0 + a1) + (a2 + a3)) * g_inv[v];
}

__device__ __forceinline__ float node_gemm(float s, float xv,
                                           const float* wl, const float* wr,
                                           float bias) {
    float acc = bias;
#pragma unroll
    for (int k = 0; k < 32; k++) {
        acc = fmaf(__shfl_sync(FULLMASK, s,  k), wl[k], acc);
        acc = fmaf(__shfl_sync(FULLMASK, xv, k), wr[k], acc);
    }
    return fmaxf(acc, 0.0f);
}

// layer 1: all nodes, X = input x, out = g_h1
__global__ void __launch_bounds__(256) k_layer1(const float* __restrict__ X,
                                                const float* __restrict__ Wl,
                                                const float* __restrict__ bl,
                                                const float* __restrict__ Wr) {
    int lane = threadIdx.x & 31;
    int warp = (blockIdx.x * blockDim.x + threadIdx.x) >> 5;
    int nw   = (gridDim.x * blockDim.x) >> 5;
    float wl[32], wr[32];
#pragma unroll
    for (int k = 0; k < 32; k++) { wl[k] = Wl[k * 32 + lane]; wr[k] = Wr[k * 32 + lane]; }
    float bias = bl[lane];
    for (int v = warp; v < NN; v += nw) {
        float s  = gather_mean(X, v, lane);
        float xv = X[(size_t)v * 32 + lane];
        g_h1[(size_t)v * 32 + lane] = node_gemm(s, xv, wl, wr, bias);
    }
}

// layer 2: flagged nodes only, X = g_h1, out = g_h2
__global__ void __launch_bounds__(256) k_layer2(const float* __restrict__ Wl,
                                                const float* __restrict__ bl,
                                                const float* __restrict__ Wr) {
    int lane = threadIdx.x & 31;
    int warp = (blockIdx.x * blockDim.x + threadIdx.x) >> 5;
    int nw   = (gridDim.x * blockDim.x) >> 5;
    float wl[32], wr[32];
#pragma unroll
    for (int k = 0; k < 32; k++) { wl[k] = Wl[k * 32 + lane]; wr[k] = Wr[k * 32 + lane]; }
    float bias = bl[lane];
    int nn = g_nn;
    for (int i = warp; i < nn; i += nw) {
        int v = g_nlist[i];
        float s  = gather_mean(g_h1, v, lane);
        float xv = g_h1[(size_t)v * 32 + lane];
        g_h2[(size_t)v * 32 + lane] = node_gemm(s, xv, wl, wr, bias);
    }
}

// layer 3 + output head: nodes [0, NA), X = g_h2
__global__ void __launch_bounds__(256) k_layer3_out(const float* __restrict__ Wl,
                                                    const float* __restrict__ bl,
                                                    const float* __restrict__ Wr,
                                                    const float* __restrict__ Wo,
                                                    const float* __restrict__ bo,
                                                    float* __restrict__ out) {
    int lane = threadIdx.x & 31;
    int warp = (blockIdx.x * blockDim.x + threadIdx.x) >> 5;
    int nw   = (gridDim.x * blockDim.x) >> 5;
    float wl[32], wr[32], wo[32];
#pragma unroll
    for (int k = 0; k < 32; k++) {
        wl[k] = Wl[k * 32 + lane];
        wr[k] = Wr[k * 32 + lane];
        wo[k] = Wo[k * 8 + (lane & 7)];
    }
    float bias = bl[lane];
    float bob  = bo[lane & 7];
    for (int v = warp; v < NA; v += nw) {
        float s  = gather_mean(g_h2, v, lane);
        float xv = g_h2[(size_t)v * 32 + lane];
        float h  = node_gemm(s, xv, wl, wr, bias);
        float o  = bob;
#pragma unroll
        for (int k = 0; k < 32; k++)
            o = fmaf(__shfl_sync(FULLMASK, h, k), wo[k], o);
        if (lane < 8) out[v * 8 + lane] = o;
    }
}

// ---------------- launch ----------------
extern "C" void kernel_launch(void* const* d_in, const int* in_sizes, int n_in,
                              void* d_out, int out_size) {
    const float* x   = (const float*)d_in[0];
    const void*  ei  = d_in[1];                 // int32 or int64, detected on device
    const float* Wl1 = (const float*)d_in[2];
    const float* bl1 = (const float*)d_in[3];
    const float* Wr1 = (const float*)d_in[4];
    const float* Wl2 = (const float*)d_in[5];
    const float* bl2 = (const float*)d_in[6];
    const float* Wr2 = (const float*)d_in[7];
    const float* Wl3 = (const float*)d_in[8];
    const float* bl3 = (const float*)d_in[9];
    const float* Wr3 = (const float*)d_in[10];
    const float* Wo  = (const float*)d_in[11];
    const float* bo  = (const float*)d_in[12];
    float* out = (float*)d_out;

    const int EB = (NE + 255) / 256;

    k_init <<<NB, 256>>>(ei);
    k_count<<<EB, 256>>>(ei);
    k_scan <<<1, SCANT>>>();
    k_place<<<EB, 256>>>(ei);

    k_layer1<<<592, 256>>>(x, Wl1, bl1, Wr1);
    k_layer2<<<592, 256>>>(Wl2, bl2, Wr2);
    k_layer3_out<<<64, 256>>>(Wl3, bl3, Wr3, Wo, bo, out);
}

// round 11
// speedup vs baseline: 2.3190x; 2.3190x over previous
#include <cuda_runtime.h>

#define NN   100000
#define NE   1600000
#define NA   1000
#define NB   ((NN + 255) / 256)          // 391 scan blocks
#define FULLMASK 0xffffffffu

// ---------------- scratch (static __device__ globals; no allocs) ----------------
__device__ __align__(16) float g_h1 [NN * 32];   // layer-1 output (all nodes)
__device__ __align__(16) float g_h2 [NN * 32];   // layer-2 output (flagged nodes only)
__device__ float         g_inv[NN];              // 1 / max(indeg, 1)
__device__ int           g_cnt[NN];              // in-degree
__device__ int           g_off[NN];              // CSR row offsets (exclusive scan of cnt)
__device__ int           g_pos[NN];              // placement cursors
__device__ int           g_csr[NE];              // src ids grouped by dst
__device__ int           g_bsum[NB];             // scan block partials
__device__ unsigned char g_need[NN];             // nodes whose h2 feeds the output cone
__device__ int           g_nlist[NN];            // compacted list of flagged nodes
__device__ int           g_nn;                   // #flagged
__device__ int           g_is64;                 // runtime-detected edge dtype

// ---------------- dtype detection (1 warp, parallel) ----------------
// int32 buffer read as int64 packs two ids/word -> values >= 2^32 >> NN.
__global__ void k_detect(const void* ei) {
    const long long* p = (const long long*)ei;
    unsigned long long v = (unsigned long long)p[threadIdx.x];
    unsigned ok = __ballot_sync(FULLMASK, v < (unsigned long long)NN);
    if (threadIdx.x == 0) g_is64 = (ok == FULLMASK) ? 1 : 0;
}

// ---------------- init ----------------
__global__ void k_init() {
    int v = blockIdx.x * 256 + threadIdx.x;
    if (v < NN) { g_cnt[v] = 0; g_need[v] = (v < NA) ? 1 : 0; }
    if (v == 0) g_nn = 0;
}

// ---------------- count degrees + mark layer-3 cone ----------------
__global__ void k_count(const void* ei) {
    int e = blockIdx.x * 256 + threadIdx.x;
    if (e >= NE) return;
    int src, dst;
    if (g_is64) {
        const long long* p = (const long long*)ei;
        src = (int)p[e]; dst = (int)p[NE + e];
    } else {
        const int* p = (const int*)ei;
        src = p[e]; dst = p[NE + e];
    }
    atomicAdd(&g_cnt[dst], 1);
    if (dst < NA) g_need[src] = 1;
}

// ---------------- exclusive scan of g_cnt (3 kernels, round-8 proven) ----------
__global__ void k_scanA() {
    __shared__ int sh[256];
    int v = blockIdx.x * 256 + threadIdx.x;
    int c = (v < NN) ? g_cnt[v] : 0;
    sh[threadIdx.x] = c;
    __syncthreads();
#pragma unroll
    for (int d = 1; d < 256; d <<= 1) {
        int t = (threadIdx.x >= d) ? sh[threadIdx.x - d] : 0;
        __syncthreads();
        sh[threadIdx.x] += t;
        __syncthreads();
    }
    if (v < NN) g_off[v] = sh[threadIdx.x] - c;           // exclusive within block
    if (threadIdx.x == 255) g_bsum[blockIdx.x] = sh[255]; // block total
}

__global__ void k_scanB() {   // single block of 512, NB <= 512
    __shared__ int sh[512];
    int t = threadIdx.x;
    int c = (t < NB) ? g_bsum[t] : 0;
    sh[t] = c;
    __syncthreads();
#pragma unroll
    for (int d = 1; d < 512; d <<= 1) {
        int u = (t >= d) ? sh[t - d] : 0;
        __syncthreads();
        sh[t] += u;
        __syncthreads();
    }
    if (t < NB) g_bsum[t] = sh[t] - c;                    // exclusive block prefix
}

__global__ void k_scanC() {   // finalize offsets, cursors, inv-degree, flagged list
    int v = blockIdx.x * 256 + threadIdx.x;
    if (v >= NN) return;
    int off = g_off[v] + g_bsum[v >> 8];
    g_off[v] = off;
    g_pos[v] = off;
    int c = g_cnt[v];
    g_inv[v] = 1.0f / (float)(c > 1 ? c : 1);
    if (g_need[v]) { int i = atomicAdd(&g_nn, 1); g_nlist[i] = v; }
}

// ---------------- CSR placement ----------------
__global__ void k_place(const void* ei) {
    int e = blockIdx.x * 256 + threadIdx.x;
    if (e >= NE) return;
    int src, dst;
    if (g_is64) {
        const long long* p = (const long long*)ei;
        src = (int)p[e]; dst = (int)p[NE + e];
    } else {
        const int* p = (const int*)ei;
        src = p[e]; dst = p[NE + e];
    }
    int p_ = atomicAdd(&g_pos[dst], 1);
    g_csr[p_] = src;
}

// ---------------- fused gather + node GEMM ----------------
// Round-8 shfl-broadcast structure (identical loads), but 4 independent
// accumulator chains -> per-warp MLP 1 -> 4 without any redundant loads.
__device__ __forceinline__ float gather_mean(const float* __restrict__ X,
                                             int v, int lane) {
    int beg = g_off[v], cnt = g_cnt[v];
    float a0 = 0.f, a1 = 0.f, a2 = 0.f, a3 = 0.f;
    for (int base = 0; base < cnt; base += 32) {
        int idx = base + lane;
        int eid = (idx < cnt) ? g_csr[beg + idx] : 0;
        int n   = min(32, cnt - base);
        int j = 0;
        for (; j + 4 <= n; j += 4) {
            int s0 = __shfl_sync(FULLMASK, eid, j + 0);
            int s1 = __shfl_sync(FULLMASK, eid, j + 1);
            int s2 = __shfl_sync(FULLMASK, eid, j + 2);
            int s3 = __shfl_sync(FULLMASK, eid, j + 3);
            a0 += X[(size_t)s0 * 32 + lane];
            a1 += X[(size_t)s1 * 32 + lane];
            a2 += X[(size_t)s2 * 32 + lane];
            a3 += X[(size_t)s3 * 32 + lane];
        }
        for (; j < n; j++) {
            int s0 = __shfl_sync(FULLMASK, eid, j);
            a0 += X[(size_t)s0 * 32 + lane];
        }
    }
    return ((a0 + a1) + (a2 + a3)) * g_inv[v];
}

__device__ __forceinline__ float node_gemm(float s, float xv,
                                           const float* wl, const float* wr,
                                           float bias) {
    float acc = bias;
#pragma unroll
    for (int k = 0; k < 32; k++) {
        acc = fmaf(__shfl_sync(FULLMASK, s,  k), wl[k], acc);
        acc = fmaf(__shfl_sync(FULLMASK, xv, k), wr[k], acc);
    }
    return fmaxf(acc, 0.0f);
}

// layer 1: all nodes, X = input x, out = g_h1
__global__ void __launch_bounds__(256) k_layer1(const float* __restrict__ X,
                                                const float* __restrict__ Wl,
                                                const float* __restrict__ bl,
                                                const float* __restrict__ Wr) {
    int lane = threadIdx.x & 31;
    int warp = (blockIdx.x * blockDim.x + threadIdx.x) >> 5;
    int nw   = (gridDim.x * blockDim.x) >> 5;
    float wl[32], wr[32];
#pragma unroll
    for (int k = 0; k < 32; k++) { wl[k] = Wl[k * 32 + lane]; wr[k] = Wr[k * 32 + lane]; }
    float bias = bl[lane];
    for (int v = warp; v < NN; v += nw) {
        float s  = gather_mean(X, v, lane);
        float xv = X[(size_t)v * 32 + lane];
        g_h1[(size_t)v * 32 + lane] = node_gemm(s, xv, wl, wr, bias);
    }
}

// layer 2: flagged nodes only, X = g_h1, out = g_h2
__global__ void __launch_bounds__(256) k_layer2(const float* __restrict__ Wl,
                                                const float* __restrict__ bl,
                                                const float* __restrict__ Wr) {
    int lane = threadIdx.x & 31;
    int warp = (blockIdx.x * blockDim.x + threadIdx.x) >> 5;
    int nw   = (gridDim.x * blockDim.x) >> 5;
    float wl[32], wr[32];
#pragma unroll
    for (int k = 0; k < 32; k++) { wl[k] = Wl[k * 32 + lane]; wr[k] = Wr[k * 32 + lane]; }
    float bias = bl[lane];
    int nn = g_nn;
    for (int i = warp; i < nn; i += nw) {
        int v = g_nlist[i];
        float s  = gather_mean(g_h1, v, lane);
        float xv = g_h1[(size_t)v * 32 + lane];
        g_h2[(size_t)v * 32 + lane] = node_gemm(s, xv, wl, wr, bias);
    }
}

// layer 3 + output head: nodes [0, NA), X = g_h2
__global__ void __launch_bounds__(256) k_layer3_out(const float* __restrict__ Wl,
                                                    const float* __restrict__ bl,
                                                    const float* __restrict__ Wr,
                                                    const float* __restrict__ Wo,
                                                    const float* __restrict__ bo,
                                                    float* __restrict__ out) {
    int lane = threadIdx.x & 31;
    int warp = (blockIdx.x * blockDim.x + threadIdx.x) >> 5;
    int nw   = (gridDim.x * blockDim.x) >> 5;
    float wl[32], wr[32], wo[32];
#pragma unroll
    for (int k = 0; k < 32; k++) {
        wl[k] = Wl[k * 32 + lane];
        wr[k] = Wr[k * 32 + lane];
        wo[k] = Wo[k * 8 + (lane & 7)];
    }
    float bias = bl[lane];
    float bob  = bo[lane & 7];
    for (int v = warp; v < NA; v += nw) {
        float s  = gather_mean(g_h2, v, lane);
        float xv = g_h2[(size_t)v * 32 + lane];
        float h  = node_gemm(s, xv, wl, wr, bias);
        float o  = bob;
#pragma unroll
        for (int k = 0; k < 32; k++)
            o = fmaf(__shfl_sync(FULLMASK, h, k), wo[k], o);
        if (lane < 8) out[v * 8 + lane] = o;
    }
}

// ---------------- launch ----------------
extern "C" void kernel_launch(void* const* d_in, const int* in_sizes, int n_in,
                              void* d_out, int out_size) {
    const float* x   = (const float*)d_in[0];
    const void*  ei  = d_in[1];                 // int32 or int64, detected on device
    const float* Wl1 = (const float*)d_in[2];
    const float* bl1 = (const float*)d_in[3];
    const float* Wr1 = (const float*)d_in[4];
    const float* Wl2 = (const float*)d_in[5];
    const float* bl2 = (const float*)d_in[6];
    const float* Wr2 = (const float*)d_in[7];
    const float* Wl3 = (const float*)d_in[8];
    const float* bl3 = (const float*)d_in[9];
    const float* Wr3 = (const float*)d_in[10];
    const float* Wo  = (const float*)d_in[11];
    const float* bo  = (const float*)d_in[12];
    float* out = (float*)d_out;

    const int EB = (NE + 255) / 256;

    k_detect<<<1, 32>>>(ei);
    k_init  <<<NB, 256>>>();
    k_count <<<EB, 256>>>(ei);
    k_scanA <<<NB, 256>>>();
    k_scanB <<<1, 512>>>();
    k_scanC <<<NB, 256>>>();
    k_place <<<EB, 256>>>(ei);

    k_layer1<<<592, 256>>>(x, Wl1, bl1, Wr1);
    k_layer2<<<592, 256>>>(Wl2, bl2, Wr2);
    k_layer3_out<<<64, 256>>>(Wl3, bl3, Wr3, Wo, bo, out);
}

// round 13
// speedup vs baseline: 2.5507x; 1.0999x over previous
#include <cuda_runtime.h>

#define NN   100000
#define NE   1600000
#define NA   1000
#define NB   ((NN + 255) / 256)          // 391 scan blocks
#define FULLMASK 0xffffffffu

// ---------------- scratch (static __device__ globals; no allocs) ----------------
// NOTE: device globals are referenced ONLY inside device code (host-side use of
// the symbol passes the host shadow address, which ATS happily dereferences
// into host memory -> silent corruption; that was round 12's bug).
__device__ __align__(16) float g_agg[NN * 32];   // scaled neighbor mean (per layer)
__device__ __align__(16) float g_h1 [NN * 32];   // layer-1 output (all nodes)
__device__ __align__(16) float g_h2 [NN * 32];   // layer-2 output (flagged nodes only)
__device__ float         g_inv[NN];              // 1 / max(indeg, 1)
__device__ int           g_cnt[NN];              // in-degree
__device__ int           g_off[NN];              // CSR row offsets
__device__ int           g_pos[NN];              // placement cursors
__device__ int           g_csr[NE];              // src ids grouped by dst
__device__ int           g_bsum[NB];             // scan block partials
__device__ unsigned char g_need[NN];             // nodes whose h2 feeds the output cone
__device__ int           g_nlist[NN];            // compacted list of flagged nodes
__device__ int           g_nn;                   // #flagged
__device__ int           g_is64;                 // runtime-detected edge dtype

// ---------------- init + dtype detection (warp-parallel probe in block 0) ------
// int32 buffer read as int64 packs two ids/word -> values >= 2^32 >> NN.
__global__ void k_init(const void* ei) {
    int v = blockIdx.x * 256 + threadIdx.x;
    if (v < NN) { g_cnt[v] = 0; g_need[v] = (v < NA) ? 1 : 0; }
    if (blockIdx.x == 0 && threadIdx.x < 32) {
        const long long* p = (const long long*)ei;
        unsigned long long w = (unsigned long long)p[threadIdx.x];
        unsigned ok = __ballot_sync(FULLMASK, w < (unsigned long long)NN);
        if (threadIdx.x == 0) { g_is64 = (ok == FULLMASK) ? 1 : 0; g_nn = 0; }
    }
}

// ---------------- count degrees + mark layer-3 cone (4 edges/thread) ----------
__global__ void k_count(const void* ei) {
    int base = blockIdx.x * 1024 + threadIdx.x;
    int is64 = g_is64;
#pragma unroll
    for (int k = 0; k < 4; k++) {
        int e = base + k * 256;
        if (e >= NE) break;
        int src, dst;
        if (is64) {
            const long long* p = (const long long*)ei;
            src = (int)p[e]; dst = (int)p[NE + e];
        } else {
            const int* p = (const int*)ei;
            src = p[e]; dst = p[NE + e];
        }
        atomicAdd(&g_cnt[dst], 1);
        if (dst < NA) g_need[src] = 1;
    }
}

// ---------------- exclusive scan of g_cnt (3 kernels, round-8 proven) ----------
__global__ void k_scanA() {
    __shared__ int sh[256];
    int v = blockIdx.x * 256 + threadIdx.x;
    int c = (v < NN) ? g_cnt[v] : 0;
    sh[threadIdx.x] = c;
    __syncthreads();
#pragma unroll
    for (int d = 1; d < 256; d <<= 1) {
        int t = (threadIdx.x >= d) ? sh[threadIdx.x - d] : 0;
        __syncthreads();
        sh[threadIdx.x] += t;
        __syncthreads();
    }
    if (v < NN) g_off[v] = sh[threadIdx.x] - c;
    if (threadIdx.x == 255) g_bsum[blockIdx.x] = sh[255];
}

__global__ void k_scanB() {   // single block of 512, NB <= 512
    __shared__ int sh[512];
    int t = threadIdx.x;
    int c = (t < NB) ? g_bsum[t] : 0;
    sh[t] = c;
    __syncthreads();
#pragma unroll
    for (int d = 1; d < 512; d <<= 1) {
        int u = (t >= d) ? sh[t - d] : 0;
        __syncthreads();
        sh[t] += u;
        __syncthreads();
    }
    if (t < NB) g_bsum[t] = sh[t] - c;
}

__global__ void k_scanC() {
    int v = blockIdx.x * 256 + threadIdx.x;
    if (v >= NN) return;
    int off = g_off[v] + g_bsum[v >> 8];
    g_off[v] = off;
    g_pos[v] = off;
    int c = g_cnt[v];
    g_inv[v] = 1.0f / (float)(c > 1 ? c : 1);
    if (g_need[v]) { int i = atomicAdd(&g_nn, 1); g_nlist[i] = v; }
}

// ---------------- CSR placement (4 edges/thread for atomic MLP) --------------
__global__ void k_place(const void* ei) {
    int base = blockIdx.x * 1024 + threadIdx.x;
    int is64 = g_is64;
#pragma unroll
    for (int k = 0; k < 4; k++) {
        int e = base + k * 256;
        if (e >= NE) break;
        int src, dst;
        if (is64) {
            const long long* p = (const long long*)ei;
            src = (int)p[e]; dst = (int)p[NE + e];
        } else {
            const int* p = (const int*)ei;
            src = p[e]; dst = p[NE + e];
        }
        int p_ = atomicAdd(&g_pos[dst], 1);
        g_csr[p_] = src;
    }
}

// ---------------- gather-only kernel: g_agg[v] = mean of X over in-neighbors ---
// Low-register (no weights) -> high occupancy; 4 independent accumulator
// chains give MLP 4 with identical loads.
// MODE: 0=all nodes, 1=nlist, 2=v<NA.   SRC: 0=param, 1=g_h1, 2=g_h2.
template <int MODE, int SRC>
__global__ void __launch_bounds__(256) k_gather(const float* __restrict__ Xp) {
    const float* X = (SRC == 0) ? Xp : (SRC == 1 ? g_h1 : g_h2);
    int lane = threadIdx.x & 31;
    int warp = (blockIdx.x * blockDim.x + threadIdx.x) >> 5;
    int nw   = (gridDim.x * blockDim.x) >> 5;
    int total = (MODE == 0) ? NN : (MODE == 1 ? g_nn : NA);
    for (int i = warp; i < total; i += nw) {
        int v = (MODE == 1) ? g_nlist[i] : i;
        int beg = g_off[v], cnt = g_cnt[v];
        float a0 = 0.f, a1 = 0.f, a2 = 0.f, a3 = 0.f;
        for (int base = 0; base < cnt; base += 32) {
            int idx = base + lane;
            int eid = (idx < cnt) ? g_csr[beg + idx] : 0;
            int n   = min(32, cnt - base);
            int j = 0;
            for (; j + 4 <= n; j += 4) {
                int s0 = __shfl_sync(FULLMASK, eid, j + 0);
                int s1 = __shfl_sync(FULLMASK, eid, j + 1);
                int s2 = __shfl_sync(FULLMASK, eid, j + 2);
                int s3 = __shfl_sync(FULLMASK, eid, j + 3);
                a0 += X[(size_t)s0 * 32 + lane];
                a1 += X[(size_t)s1 * 32 + lane];
                a2 += X[(size_t)s2 * 32 + lane];
                a3 += X[(size_t)s3 * 32 + lane];
            }
            for (; j < n; j++) {
                int s0 = __shfl_sync(FULLMASK, eid, j);
                a0 += X[(size_t)s0 * 32 + lane];
            }
        }
        g_agg[(size_t)v * 32 + lane] = ((a0 + a1) + (a2 + a3)) * g_inv[v];
    }
}

// ---------------- GEMM kernel: H = relu(agg@Wl + bl + X@Wr) --------------------
// Fat-register weights, streaming (2 coalesced loads per node) -> latency-
// insensitive. MODE: 0=all nodes, 1=nlist. SRC: 0=param, 1=g_h1. DST: 1/2.
__device__ __forceinline__ float node_gemm(float s, float xv,
                                           const float* wl, const float* wr,
                                           float bias) {
    float acc = bias;
#pragma unroll
    for (int k = 0; k < 32; k++) {
        acc = fmaf(__shfl_sync(FULLMASK, s,  k), wl[k], acc);
        acc = fmaf(__shfl_sync(FULLMASK, xv, k), wr[k], acc);
    }
    return fmaxf(acc, 0.0f);
}

template <int MODE, int SRC, int DST>
__global__ void __launch_bounds__(256) k_gemm(const float* __restrict__ Xp,
                                              const float* __restrict__ Wl,
                                              const float* __restrict__ bl,
                                              const float* __restrict__ Wr) {
    const float* X = (SRC == 0) ? Xp : g_h1;
    float*       H = (DST == 1) ? g_h1 : g_h2;
    int lane = threadIdx.x & 31;
    int warp = (blockIdx.x * blockDim.x + threadIdx.x) >> 5;
    int nw   = (gridDim.x * blockDim.x) >> 5;
    float wl[32], wr[32];
#pragma unroll
    for (int k = 0; k < 32; k++) { wl[k] = Wl[k * 32 + lane]; wr[k] = Wr[k * 32 + lane]; }
    float bias = bl[lane];
    int total = (MODE == 0) ? NN : g_nn;
    for (int i = warp; i < total; i += nw) {
        int v = (MODE == 1) ? g_nlist[i] : i;
        float s  = g_agg[(size_t)v * 32 + lane];
        float xv = X[(size_t)v * 32 + lane];
        H[(size_t)v * 32 + lane] = node_gemm(s, xv, wl, wr, bias);
    }
}

// layer 3 GEMM fused with output head over nodes [0, NA)
__global__ void __launch_bounds__(256) k_gemm3_out(const float* __restrict__ Wl,
                                                   const float* __restrict__ bl,
                                                   const float* __restrict__ Wr,
                                                   const float* __restrict__ Wo,
                                                   const float* __restrict__ bo,
                                                   float* __restrict__ out) {
    int lane = threadIdx.x & 31;
    int warp = (blockIdx.x * blockDim.x + threadIdx.x) >> 5;
    int nw   = (gridDim.x * blockDim.x) >> 5;
    float wl[32], wr[32], wo[32];
#pragma unroll
    for (int k = 0; k < 32; k++) {
        wl[k] = Wl[k * 32 + lane];
        wr[k] = Wr[k * 32 + lane];
        wo[k] = Wo[k * 8 + (lane & 7)];
    }
    float bias = bl[lane];
    float bob  = bo[lane & 7];
    for (int v = warp; v < NA; v += nw) {
        float s  = g_agg[(size_t)v * 32 + lane];
        float xv = g_h2 [(size_t)v * 32 + lane];
        float h  = node_gemm(s, xv, wl, wr, bias);
        float o  = bob;
#pragma unroll
        for (int k = 0; k < 32; k++)
            o = fmaf(__shfl_sync(FULLMASK, h, k), wo[k], o);
        if (lane < 8) out[v * 8 + lane] = o;
    }
}

// ---------------- launch ----------------
extern "C" void kernel_launch(void* const* d_in, const int* in_sizes, int n_in,
                              void* d_out, int out_size) {
    const float* x   = (const float*)d_in[0];
    const void*  ei  = d_in[1];                 // int32 or int64, detected on device
    const float* Wl1 = (const float*)d_in[2];
    const float* bl1 = (const float*)d_in[3];
    const float* Wr1 = (const float*)d_in[4];
    const float* Wl2 = (const float*)d_in[5];
    const float* bl2 = (const float*)d_in[6];
    const float* Wr2 = (const float*)d_in[7];
    const float* Wl3 = (const float*)d_in[8];
    const float* bl3 = (const float*)d_in[9];
    const float* Wr3 = (const float*)d_in[10];
    const float* Wo  = (const float*)d_in[11];
    const float* bo  = (const float*)d_in[12];
    float* out = (float*)d_out;

    const int EB4 = (NE + 1023) / 1024;     // 4-edges-per-thread grids

    k_init <<<NB, 256>>>(ei);
    k_count<<<EB4, 256>>>(ei);
    k_scanA<<<NB, 256>>>();
    k_scanB<<<1, 512>>>();
    k_scanC<<<NB, 256>>>();
    k_place<<<EB4, 256>>>(ei);

    // layer 1: full graph
    k_gather<0, 0><<<1184, 256>>>(x);
    k_gemm<0, 0, 1><<<592, 256>>>(x, Wl1, bl1, Wr1);
    // layer 2: output cone only
    k_gather<1, 1><<<1184, 256>>>(nullptr);
    k_gemm<1, 1, 2><<<592, 256>>>(nullptr, Wl2, bl2, Wr2);
    // layer 3 + head: first NA nodes
    k_gather<2, 2><<<64, 256>>>(nullptr);
    k_gemm3_out<<<64, 256>>>(Wl3, bl3, Wr3, Wo, bo, out);
}

// round 14
// speedup vs baseline: 3.0044x; 1.1779x over previous
#include <cuda_runtime.h>

#define NN   100000
#define NE   1600000
#define NA   1000
#define NB   ((NN + 255) / 256)          // 391 scan blocks
#define FULLMASK 0xffffffffu

// ---------------- scratch (static __device__ globals; no allocs) ----------------
// Device globals are referenced ONLY inside device code (host-side symbol use
// passes the host shadow address; ATS dereferences it into host memory).
__device__ __align__(16) float g_h1 [NN * 32];   // layer-1 output (all nodes)
__device__ __align__(16) float g_h2 [NN * 32];   // layer-2 output (flagged nodes only)
__device__ float         g_inv[NN];              // 1 / max(indeg, 1)
__device__ int           g_cnt[NN];              // in-degree
__device__ int           g_off[NN];              // CSR row offsets
__device__ int           g_pos[NN];              // placement cursors
__device__ int           g_csr[NE];              // src ids grouped by dst
__device__ int           g_bsum[NB];             // scan block partials
__device__ unsigned char g_need[NN];             // nodes whose h2 feeds the output cone
__device__ int           g_nlist[NN];            // compacted list of flagged nodes
__device__ int           g_nn;                   // #flagged
__device__ int           g_is64;                 // runtime-detected edge dtype

// ---------------- init + dtype detection (warp-parallel probe in block 0) ------
// int32 buffer read as int64 packs two ids/word -> values >= 2^32 >> NN.
__global__ void k_init(const void* ei) {
    int v = blockIdx.x * 256 + threadIdx.x;
    if (v < NN) { g_cnt[v] = 0; g_need[v] = (v < NA) ? 1 : 0; }
    if (blockIdx.x == 0 && threadIdx.x < 32) {
        const long long* p = (const long long*)ei;
        unsigned long long w = (unsigned long long)p[threadIdx.x];
        unsigned ok = __ballot_sync(FULLMASK, w < (unsigned long long)NN);
        if (threadIdx.x == 0) { g_is64 = (ok == FULLMASK) ? 1 : 0; g_nn = 0; }
    }
}

// ---------------- count degrees + mark layer-3 cone (4 edges/thread) ----------
__global__ void k_count(const void* ei) {
    int base = blockIdx.x * 1024 + threadIdx.x;
    int is64 = g_is64;
#pragma unroll
    for (int k = 0; k < 4; k++) {
        int e = base + k * 256;
        if (e >= NE) break;
        int src, dst;
        if (is64) {
            const long long* p = (const long long*)ei;
            src = (int)p[e]; dst = (int)p[NE + e];
        } else {
            const int* p = (const int*)ei;
            src = p[e]; dst = p[NE + e];
        }
        atomicAdd(&g_cnt[dst], 1);
        if (dst < NA) g_need[src] = 1;
    }
}

// ---------------- exclusive scan of g_cnt (3 kernels, proven) ----------------
__global__ void k_scanA() {
    __shared__ int sh[256];
    int v = blockIdx.x * 256 + threadIdx.x;
    int c = (v < NN) ? g_cnt[v] : 0;
    sh[threadIdx.x] = c;
    __syncthreads();
#pragma unroll
    for (int d = 1; d < 256; d <<= 1) {
        int t = (threadIdx.x >= d) ? sh[threadIdx.x - d] : 0;
        __syncthreads();
        sh[threadIdx.x] += t;
        __syncthreads();
    }
    if (v < NN) g_off[v] = sh[threadIdx.x] - c;
    if (threadIdx.x == 255) g_bsum[blockIdx.x] = sh[255];
}

__global__ void k_scanB() {   // single block of 512, NB <= 512
    __shared__ int sh[512];
    int t = threadIdx.x;
    int c = (t < NB) ? g_bsum[t] : 0;
    sh[t] = c;
    __syncthreads();
#pragma unroll
    for (int d = 1; d < 512; d <<= 1) {
        int u = (t >= d) ? sh[t - d] : 0;
        __syncthreads();
        sh[t] += u;
        __syncthreads();
    }
    if (t < NB) g_bsum[t] = sh[t] - c;
}

__global__ void k_scanC() {
    int v = blockIdx.x * 256 + threadIdx.x;
    if (v >= NN) return;
    int off = g_off[v] + g_bsum[v >> 8];
    g_off[v] = off;
    g_pos[v] = off;
    int c = g_cnt[v];
    g_inv[v] = 1.0f / (float)(c > 1 ? c : 1);
    if (g_need[v]) { int i = atomicAdd(&g_nn, 1); g_nlist[i] = v; }
}

// ---------------- CSR placement (4 edges/thread for atomic MLP) --------------
__global__ void k_place(const void* ei) {
    int base = blockIdx.x * 1024 + threadIdx.x;
    int is64 = g_is64;
#pragma unroll
    for (int k = 0; k < 4; k++) {
        int e = base + k * 256;
        if (e >= NE) break;
        int src, dst;
        if (is64) {
            const long long* p = (const long long*)ei;
            src = (int)p[e]; dst = (int)p[NE + e];
        } else {
            const int* p = (const int*)ei;
            src = p[e]; dst = p[NE + e];
        }
        int p_ = atomicAdd(&g_pos[dst], 1);
        g_csr[p_] = src;
    }
}

// ---------------- fused layer: gather + GEMM with SMEM weights ----------------
// Weights live in shared memory (8 KB) -> ~45 regs/thread -> 5 blocks/SM ->
// 40 warps/SM hide the gather's L2 latency, while the 4-chain gather gives
// MLP 4. LDS pattern w[k*32+lane] is lane-linear: conflict-free, 1 wavefront.
// MODE: 0=all nodes, 1=nlist. SRC: 0=param, 1=g_h1. DST: 1=g_h1, 2=g_h2.
template <int MODE, int SRC, int DST>
__global__ void __launch_bounds__(256, 5) k_layer(const float* __restrict__ Xp,
                                                  const float* __restrict__ Wl,
                                                  const float* __restrict__ bl,
                                                  const float* __restrict__ Wr) {
    __shared__ float swl[1024], swr[1024];
    for (int i = threadIdx.x; i < 1024; i += 256) {
        swl[i] = Wl[i];
        swr[i] = Wr[i];
    }
    __syncthreads();

    const float* X = (SRC == 0) ? Xp : g_h1;
    float*       H = (DST == 1) ? g_h1 : g_h2;
    int lane = threadIdx.x & 31;
    int warp = (blockIdx.x * blockDim.x + threadIdx.x) >> 5;
    int nw   = (gridDim.x * blockDim.x) >> 5;
    float bias = bl[lane];
    int total = (MODE == 0) ? NN : g_nn;

    for (int i = warp; i < total; i += nw) {
        int v = (MODE == 1) ? g_nlist[i] : i;
        int beg = g_off[v], cnt = g_cnt[v];
        // gather: 4 independent accumulator chains, identical loads
        float a0 = 0.f, a1 = 0.f, a2 = 0.f, a3 = 0.f;
        for (int base = 0; base < cnt; base += 32) {
            int idx = base + lane;
            int eid = (idx < cnt) ? g_csr[beg + idx] : 0;
            int n   = min(32, cnt - base);
            int j = 0;
            for (; j + 4 <= n; j += 4) {
                int s0 = __shfl_sync(FULLMASK, eid, j + 0);
                int s1 = __shfl_sync(FULLMASK, eid, j + 1);
                int s2 = __shfl_sync(FULLMASK, eid, j + 2);
                int s3 = __shfl_sync(FULLMASK, eid, j + 3);
                a0 += X[(size_t)s0 * 32 + lane];
                a1 += X[(size_t)s1 * 32 + lane];
                a2 += X[(size_t)s2 * 32 + lane];
                a3 += X[(size_t)s3 * 32 + lane];
            }
            for (; j < n; j++) {
                int s0 = __shfl_sync(FULLMASK, eid, j);
                a0 += X[(size_t)s0 * 32 + lane];
            }
        }
        float s  = ((a0 + a1) + (a2 + a3)) * g_inv[v];
        float xv = X[(size_t)v * 32 + lane];
        // GEMM: weights from smem
        float acc = bias;
#pragma unroll
        for (int k = 0; k < 32; k++) {
            acc = fmaf(__shfl_sync(FULLMASK, s,  k), swl[k * 32 + lane], acc);
            acc = fmaf(__shfl_sync(FULLMASK, xv, k), swr[k * 32 + lane], acc);
        }
        H[(size_t)v * 32 + lane] = fmaxf(acc, 0.0f);
    }
}

// ---------------- layer 3 fused with output head (nodes [0, NA)) --------------
__global__ void __launch_bounds__(256, 5) k_layer3_out(const float* __restrict__ Wl,
                                                       const float* __restrict__ bl,
                                                       const float* __restrict__ Wr,
                                                       const float* __restrict__ Wo,
                                                       const float* __restrict__ bo,
                                                       float* __restrict__ out) {
    __shared__ float swl[1024], swr[1024], swo[256];
    for (int i = threadIdx.x; i < 1024; i += 256) {
        swl[i] = Wl[i];
        swr[i] = Wr[i];
    }
    if (threadIdx.x < 256) swo[threadIdx.x] = Wo[threadIdx.x];
    __syncthreads();

    int lane = threadIdx.x & 31;
    int warp = (blockIdx.x * blockDim.x + threadIdx.x) >> 5;
    int nw   = (gridDim.x * blockDim.x) >> 5;
    float bias = bl[lane];
    float bob  = bo[lane & 7];

    for (int v = warp; v < NA; v += nw) {
        int beg = g_off[v], cnt = g_cnt[v];
        float a0 = 0.f, a1 = 0.f, a2 = 0.f, a3 = 0.f;
        for (int base = 0; base < cnt; base += 32) {
            int idx = base + lane;
            int eid = (idx < cnt) ? g_csr[beg + idx] : 0;
            int n   = min(32, cnt - base);
            int j = 0;
            for (; j + 4 <= n; j += 4) {
                int s0 = __shfl_sync(FULLMASK, eid, j + 0);
                int s1 = __shfl_sync(FULLMASK, eid, j + 1);
                int s2 = __shfl_sync(FULLMASK, eid, j + 2);
                int s3 = __shfl_sync(FULLMASK, eid, j + 3);
                a0 += g_h2[(size_t)s0 * 32 + lane];
                a1 += g_h2[(size_t)s1 * 32 + lane];
                a2 += g_h2[(size_t)s2 * 32 + lane];
                a3 += g_h2[(size_t)s3 * 32 + lane];
            }
            for (; j < n; j++) {
                int s0 = __shfl_sync(FULLMASK, eid, j);
                a0 += g_h2[(size_t)s0 * 32 + lane];
            }
        }
        float s  = ((a0 + a1) + (a2 + a3)) * g_inv[v];
        float xv = g_h2[(size_t)v * 32 + lane];
        float acc = bias;
#pragma unroll
        for (int k = 0; k < 32; k++) {
            acc = fmaf(__shfl_sync(FULLMASK, s,  k), swl[k * 32 + lane], acc);
            acc = fmaf(__shfl_sync(FULLMASK, xv, k), swr[k * 32 + lane], acc);
        }
        float h = fmaxf(acc, 0.0f);
        float o = bob;
#pragma unroll
        for (int k = 0; k < 32; k++)
            o = fmaf(__shfl_sync(FULLMASK, h, k), swo[k * 8 + (lane & 7)], o);
        if (lane < 8) out[v * 8 + lane] = o;
    }
}

// ---------------- launch ----------------
extern "C" void kernel_launch(void* const* d_in, const int* in_sizes, int n_in,
                              void* d_out, int out_size) {
    const float* x   = (const float*)d_in[0];
    const void*  ei  = d_in[1];                 // int32 or int64, detected on device
    const float* Wl1 = (const float*)d_in[2];
    const float* bl1 = (const float*)d_in[3];
    const float* Wr1 = (const float*)d_in[4];
    const float* Wl2 = (const float*)d_in[5];
    const float* bl2 = (const float*)d_in[6];
    const float* Wr2 = (const float*)d_in[7];
    const float* Wl3 = (const float*)d_in[8];
    const float* bl3 = (const float*)d_in[9];
    const float* Wr3 = (const float*)d_in[10];
    const float* Wo  = (const float*)d_in[11];
    const float* bo  = (const float*)d_in[12];
    float* out = (float*)d_out;

    const int EB4 = (NE + 1023) / 1024;     // 4-edges-per-thread grids

    k_init <<<NB, 256>>>(ei);
    k_count<<<EB4, 256>>>(ei);
    k_scanA<<<NB, 256>>>();
    k_scanB<<<1, 512>>>();
    k_scanC<<<NB, 256>>>();
    k_place<<<EB4, 256>>>(ei);

    // layer 1: full graph (5 blocks/SM x 148 SMs)
    k_layer<0, 0, 1><<<740, 256>>>(x, Wl1, bl1, Wr1);
    // layer 2: output cone only
    k_layer<1, 1, 2><<<740, 256>>>(nullptr, Wl2, bl2, Wr2);
    // layer 3 + head: first NA nodes
    k_layer3_out<<<64, 256>>>(Wl3, bl3, Wr3, Wo, bo, out);
}